// round 17
// baseline (speedup 1.0000x reference)
#include <cuda_runtime.h>
#include <cuda_fp16.h>
#include <math.h>

#define BB 64
#define DD 1024
#define TT 128
#define SS 128
#define EE 512
#define NCTA 256
#define NTHR 256

// ---------------- device scratch (static, no allocations) ----------------
__device__ float g_h0[BB][DD];
__device__ float g_h1[BB][DD];
__device__ float g_c0[BB][DD];
__device__ float g_c1[BB][DD];
__device__ float g_out[BB][DD];
__device__ float g_wctx[BB][DD];
__device__ float g_bias0[4 * DD];
__device__ float g_bias1[4 * DD];
__device__ __half g_Cq16[(size_t)SS * BB * DD];         // (ctx @ W_in) fp16 : [s][b][k]
__device__ __half g_ctx16[(size_t)SS * BB * DD];        // context fp16 copy
__device__ float g_part[8 * 4096 * 64];                 // split-K partials (fp32)
__device__ float g_pre[(size_t)TT * 4096 * BB];         // emb projection [t][row][b]
__device__ float g_scg[BB * SS];                        // attn scores scratch

// pre-packed fp16 m16n8k16 fragment weights: idx = ((mb*K16 + k16)*32 + lane)
__device__ uint4 g_WfE[256 * 32 * 32];    // lstm0 emb part:  4096 x 512
__device__ uint4 g_Wf0[256 * 128 * 32];   // lstm0 [out|h0]:  4096 x 2048
__device__ uint4 g_Wf1[256 * 128 * 32];   // lstm1 [h0|h1]:   4096 x 2048
__device__ uint4 g_WfO[64 * 128 * 32];    // out  [wctx|h1]:  1024 x 2048
__device__ uint4 g_WfQ[64 * 64 * 32];     // W_in^T:          1024 x 1024

__device__ unsigned g_bar_count;
__device__ volatile unsigned g_bar_epoch;

__device__ __forceinline__ float sigm(float x) { return 1.f / (1.f + __expf(-x)); }

__device__ __forceinline__ unsigned h2u(__half2 h) {
    return *(unsigned*)&h;
}
__device__ __forceinline__ void mma_f16(float* c, const unsigned* a, const unsigned* b) {
    asm volatile(
        "mma.sync.aligned.m16n8k16.row.col.f32.f16.f16.f32 "
        "{%0,%1,%2,%3}, {%4,%5,%6,%7}, {%8,%9}, {%0,%1,%2,%3};"
        : "+f"(c[0]), "+f"(c[1]), "+f"(c[2]), "+f"(c[3])
        : "r"(a[0]), "r"(a[1]), "r"(a[2]), "r"(a[3]), "r"(b[0]), "r"(b[1]));
}

// software grid barrier (256 CTAs, all resident at 2/SM)
__device__ __forceinline__ void grid_barrier() {
    __syncthreads();
    if (threadIdx.x == 0) {
        unsigned e = g_bar_epoch;
        __threadfence();
        unsigned a = atomicAdd(&g_bar_count, 1u);
        if (a == NCTA - 1) {
            g_bar_count = 0;
            __threadfence();
            atomicAdd((unsigned*)&g_bar_epoch, 1u);
        } else {
            while (g_bar_epoch == e) { }
        }
        __threadfence();
    }
    __syncthreads();
}

// ---------------- shared-mem layouts ----------------
struct SmemGemm {
    uint4 A[3][8][2][32];    // 24KB  A fp16 frags, 3-stage (8 mblocks = 128 rows)
    uint2 Bf[2][8][2][32];   // 8KB   B fp16 frags, 2-stage
};
struct SmemAttn {
    float h1s[DD];           // 4KB
    float4 wbuf[4][64];      // 4KB
};
union SmemU {
    SmemGemm g;
    SmemAttn a;
};

// ---------------- init ----------------
__global__ void init_kernel(const float* __restrict__ h0, const float* __restrict__ c0,
                            const float* __restrict__ io,
                            const float* __restrict__ bih0, const float* __restrict__ bhh0,
                            const float* __restrict__ bih1, const float* __restrict__ bhh1) {
    int i = blockIdx.x * blockDim.x + threadIdx.x;
    if (i < BB * DD) {
        ((float*)g_h0)[i] = h0[i];
        ((float*)g_h1)[i] = h0[BB * DD + i];
        ((float*)g_c0)[i] = c0[i];
        ((float*)g_c1)[i] = c0[BB * DD + i];
        ((float*)g_out)[i] = io[i];
    }
    if (i < 4 * DD) {
        g_bias0[i] = bih0[i] + bhh0[i];
        g_bias1[i] = bih1[i] + bhh1[i];
    }
}

// ---------------- context -> fp16 copy (one-time) ----------------
__global__ void ctx16_kernel(const float* __restrict__ context) {
    size_t i = (size_t)blockIdx.x * 256 + threadIdx.x;
    if (i < (size_t)SS * BB * DD) g_ctx16[i] = __float2half(context[i]);
}

// ---------------- weight fragment pack (one-time, fp16 m16n8k16 layout) ------
// Destination tag resolved in device code (host __device__-symbol args write
// host memory on GB300/ATS — rounds 7/8 bug). trans: read W1[c*ld1 + r].
__global__ void pack_kernel(const float* __restrict__ W1, int ld1, int off1,
                            const float* __restrict__ W2, int ld2, int K1w,
                            int K16tot, int mbTot, int which, int trans) {
    uint4* __restrict__ dst = (which == 0) ? g_WfE
                            : (which == 1) ? g_Wf0
                            : (which == 2) ? g_Wf1
                            : (which == 3) ? g_WfO : g_WfQ;
    size_t idx = (size_t)blockIdx.x * 256 + threadIdx.x;
    size_t total = (size_t)mbTot * K16tot * 32;
    if (idx >= total) return;
    int lane = (int)(idx & 31);
    size_t f = idx >> 5;
    int k16 = (int)(f % K16tot);
    int mb = (int)(f / K16tot);
    int g = lane >> 2, t = lane & 3;
    int r0 = mb * 16 + g, r8 = r0 + 8;
    int cA = k16 * 16 + 2 * t;
    int cB = cA + 8;
    #define LDW(r, c) (trans ? W1[(size_t)(c) * ld1 + (r)] \
                     : ((c) < K1w) ? W1[(size_t)(r) * ld1 + off1 + (c)] \
                                   : W2[(size_t)(r) * ld2 + ((c) - K1w)])
    __half2 h0 = __floats2half2_rn(LDW(r0, cA), LDW(r0, cA + 1));
    __half2 h1 = __floats2half2_rn(LDW(r8, cA), LDW(r8, cA + 1));
    __half2 h2 = __floats2half2_rn(LDW(r0, cB), LDW(r0, cB + 1));
    __half2 h3 = __floats2half2_rn(LDW(r8, cB), LDW(r8, cB + 1));
    #undef LDW
    dst[idx] = make_uint4(h2u(h0), h2u(h1), h2u(h2), h2u(h3));
}

// ---------------- pipelined fp16 GEMM core (256 threads, 8 warps) ----------
__device__ __forceinline__ void issueA(SmemGemm* sm, const uint4* __restrict__ Wf,
                                       int K16tot, int mbG0, int k16Base,
                                       int chunk, int buf, int wid, int lane) {
    int k16c = k16Base + (chunk << 1);
    #pragma unroll
    for (int j = 0; j < 2; j++) {
        int mbk = j * 8 + wid;              // 0..15
        int mbL = mbk >> 1, k16L = mbk & 1;
        const uint4* src = Wf + ((size_t)(mbG0 + mbL) * K16tot + (k16c + k16L)) * 32 + lane;
        unsigned dst = (unsigned)__cvta_generic_to_shared(&sm->A[buf][mbL][k16L][lane]);
        asm volatile("cp.async.cg.shared.global [%0], [%1], 16;" :: "r"(dst), "l"(src));
    }
    asm volatile("cp.async.commit_group;" ::: "memory");
}

// B load: each warp fills 2 slots; fp32 sources (R13 numerics).
__device__ __forceinline__ void loadB(const float* const* rp1, const float* const* rp2,
                                      int KX1, int ksBase, int chunk,
                                      int wid, int g, int t4, float pbv[2][4]) {
    int k0 = ksBase + (chunk << 5);
    #pragma unroll
    for (int j = 0; j < 2; j++) {
        int nbk = j * 8 + wid;
        int nb = nbk >> 1, k16 = nbk & 1;
        int b = nb * 8 + g;
        int kbase = k0 + k16 * 16;
        const float* s = (kbase < KX1) ? rp1[b] + kbase : rp2[b] + (kbase - KX1);
        float2 v0 = *(const float2*)(s + 2 * t4);
        float2 v1 = *(const float2*)(s + 2 * t4 + 8);
        pbv[j][0] = v0.x; pbv[j][1] = v0.y; pbv[j][2] = v1.x; pbv[j][3] = v1.y;
    }
}

// CTA tile 128 rows x 64 batch; 8 warps (4m x 2n), warp tile 32x32.
// epi 0: fp32 partials; epi 1: fp16 Cq at [(sIdx*BB+b)*DD + row].
__device__ __forceinline__ void gemm_async(
    int rowBase, int ksBase, int KS,
    const uint4* __restrict__ Wf, int K16tot,
    const float* const* rp1, const float* const* rp2, int KX1,
    float* __restrict__ partOut, SmemGemm* sm, int epi, int sIdx) {
    const int tid = threadIdx.x;
    const int wid = tid >> 5, lane = tid & 31;
    const int g = lane >> 2, t4 = lane & 3;
    const int mb0 = (wid >> 1) << 1;     // {0,2,4,6}
    const int nb0 = (wid & 1) << 2;      // {0,4}
    const int mbG0 = rowBase >> 4;
    const int k16Base = ksBase >> 4;
    const int nChunk = KS >> 5;

    float acc[2][4][4];
    #pragma unroll
    for (int i = 0; i < 2; i++)
        #pragma unroll
        for (int j = 0; j < 4; j++)
            #pragma unroll
            for (int r = 0; r < 4; r++) acc[i][j][r] = 0.f;

    issueA(sm, Wf, K16tot, mbG0, k16Base, 0, 0, wid, lane);
    if (nChunk > 1) issueA(sm, Wf, K16tot, mbG0, k16Base, 1, 1, wid, lane);
    float pb[2][4];
    loadB(rp1, rp2, KX1, ksBase, 0, wid, g, t4, pb);

    for (int i = 0; i < nChunk; i++) {
        #pragma unroll
        for (int j = 0; j < 2; j++) {
            int nbk = j * 8 + wid;
            int nbS = nbk >> 1, k16S = nbk & 1;
            __half2 hA = __floats2half2_rn(pb[j][0], pb[j][1]);
            __half2 hB = __floats2half2_rn(pb[j][2], pb[j][3]);
            sm->Bf[i & 1][nbS][k16S][lane] = make_uint2(h2u(hA), h2u(hB));
        }
        float pbn[2][4];
        if (i + 1 < nChunk) {
            loadB(rp1, rp2, KX1, ksBase, i + 1, wid, g, t4, pbn);
            asm volatile("cp.async.wait_group 1;" ::: "memory");
        } else {
            asm volatile("cp.async.wait_group 0;" ::: "memory");
        }
        __syncthreads();
        const int ab = i % 3;
        #pragma unroll
        for (int k16 = 0; k16 < 2; k16++) {
            uint4 a0 = sm->A[ab][mb0][k16][lane];
            uint4 a1 = sm->A[ab][mb0 + 1][k16][lane];
            #pragma unroll
            for (int nj = 0; nj < 4; nj++) {
                uint2 bb = sm->Bf[i & 1][nb0 + nj][k16][lane];
                mma_f16(acc[0][nj], (const unsigned*)&a0, (const unsigned*)&bb);
                mma_f16(acc[1][nj], (const unsigned*)&a1, (const unsigned*)&bb);
            }
        }
        if (i + 2 < nChunk)
            issueA(sm, Wf, K16tot, mbG0, k16Base, i + 2, (i + 2) % 3, wid, lane);
        if (i + 1 < nChunk) {
            #pragma unroll
            for (int j = 0; j < 2; j++) {
                pb[j][0] = pbn[j][0]; pb[j][1] = pbn[j][1];
                pb[j][2] = pbn[j][2]; pb[j][3] = pbn[j][3];
            }
        }
    }
    __syncthreads();   // protect smem reuse by the next phase

    if (epi == 0) {
        #pragma unroll
        for (int mi = 0; mi < 2; mi++) {
            int rb = rowBase + (mb0 + mi) * 16 + g;
            #pragma unroll
            for (int nj = 0; nj < 4; nj++) {
                int col = (nb0 + nj) * 8 + 2 * t4;
                *(float2*)&partOut[(size_t)rb * 64 + col]       = make_float2(acc[mi][nj][0], acc[mi][nj][1]);
                *(float2*)&partOut[(size_t)(rb + 8) * 64 + col] = make_float2(acc[mi][nj][2], acc[mi][nj][3]);
            }
        }
    } else {
        #pragma unroll
        for (int mi = 0; mi < 2; mi++) {
            int rb = rowBase + (mb0 + mi) * 16 + g;
            #pragma unroll
            for (int nj = 0; nj < 4; nj++) {
                int col = (nb0 + nj) * 8 + 2 * t4;
                g_Cq16[((size_t)sIdx * BB + col)     * DD + rb]     = __float2half(acc[mi][nj][0]);
                g_Cq16[((size_t)sIdx * BB + col + 1) * DD + rb]     = __float2half(acc[mi][nj][1]);
                g_Cq16[((size_t)sIdx * BB + col)     * DD + rb + 8] = __float2half(acc[mi][nj][2]);
                g_Cq16[((size_t)sIdx * BB + col + 1) * DD + rb + 8] = __float2half(acc[mi][nj][3]);
            }
        }
    }
}

// ---------------- Cq precompute (one-time): Cq[s][b][k] = ctx[s][b][:].Win[:,k]
__global__ __launch_bounds__(NTHR, 2) void cq16_kernel(const float* __restrict__ context) {
    extern __shared__ char dynsm[];
    SmemGemm* sm = (SmemGemm*)dynsm;
    __shared__ const float* rp1[64];
    const int s = blockIdx.y;
    if (threadIdx.x < 64)
        rp1[threadIdx.x] = context + (size_t)(s * BB + threadIdx.x) * DD;
    __syncthreads();
    gemm_async(blockIdx.x * 128, 0, DD, g_WfQ, 64,
               rp1, rp1, 1 << 30, nullptr, sm, 1, s);
}

// ---------------- emb projection (one-time) ----------------
__global__ __launch_bounds__(NTHR, 2) void pre_emb_kernel(
    const int* __restrict__ input, const float* __restrict__ word_lut) {
    extern __shared__ char dynsm[];
    SmemGemm* sm = (SmemGemm*)dynsm;
    __shared__ const float* rp1[64];
    const int t = blockIdx.y;
    if (threadIdx.x < 64) {
        int tok = input[threadIdx.x * TT + t];
        rp1[threadIdx.x] = word_lut + (size_t)tok * EE;
    }
    __syncthreads();
    gemm_async(blockIdx.x * 128, 0, EE, g_WfE, EE / 16,
               rp1, rp1, 1 << 30, g_pre + (size_t)t * 4096 * 64, sm, 0, 0);
}

// ---------------- step phases ----------------
__device__ __forceinline__ void cell_phase(int layer, int t) {
    int e = blockIdx.x * NTHR + threadIdx.x;    // 65536 = BB*DD
    int b = e & 63, d = e >> 6;
    const float* bias = layer ? g_bias1 : g_bias0;
    float gg[4];
    #pragma unroll
    for (int gate = 0; gate < 4; gate++) {
        int row = gate * DD + d;
        float s = bias[row];
        if (layer == 0) s += g_pre[((size_t)t * 4096 + row) * 64 + b];
        #pragma unroll
        for (int ks = 0; ks < 8; ks++)
            s += g_part[((size_t)ks * 4096 + row) * 64 + b];
        gg[gate] = s;
    }
    if (layer) {
        float cn = sigm(gg[1]) * g_c1[b][d] + sigm(gg[0]) * tanhf(gg[2]);
        g_c1[b][d] = cn;
        g_h1[b][d] = sigm(gg[3]) * tanhf(cn);
    } else {
        float cn = sigm(gg[1]) * g_c0[b][d] + sigm(gg[0]) * tanhf(gg[2]);
        g_c0[b][d] = cn;
        g_h0[b][d] = sigm(gg[3]) * tanhf(cn);
    }
}

// attn phase A: 4 CTAs/batch, each computes its 32-score slice (no duplication)
__device__ __forceinline__ void attnA_phase(SmemAttn* sm) {
    const int tid = threadIdx.x;
    const int b = blockIdx.x >> 2;
    const int q = blockIdx.x & 3;
    const int lane = tid & 31, wid = tid >> 5;

    for (int i = tid; i < DD; i += NTHR) sm->h1s[i] = g_h1[b][i];
    __syncthreads();

    // 8 warps x 4 scores = 32 scores for this quarter
    #pragma unroll
    for (int i = 0; i < 4; i++) {
        int s = q * 32 + wid * 4 + i;
        const uint4* cp = (const uint4*)(g_Cq16 + (size_t)(s * BB + b) * DD);
        float p = 0.f;
        #pragma unroll
        for (int jj = 0; jj < 4; jj++) {
            int u = lane + jj * 32;
            uint4 qv = cp[u];
            const __half2* hh = (const __half2*)&qv;
            float2 f0 = __half22float2(hh[0]);
            float2 f1 = __half22float2(hh[1]);
            float2 f2 = __half22float2(hh[2]);
            float2 f3 = __half22float2(hh[3]);
            int base = u * 8;
            p += f0.x * sm->h1s[base]     + f0.y * sm->h1s[base + 1] +
                 f1.x * sm->h1s[base + 2] + f1.y * sm->h1s[base + 3] +
                 f2.x * sm->h1s[base + 4] + f2.y * sm->h1s[base + 5] +
                 f3.x * sm->h1s[base + 6] + f3.y * sm->h1s[base + 7];
        }
        #pragma unroll
        for (int off = 16; off; off >>= 1) p += __shfl_xor_sync(~0u, p, off);
        if (lane == 0) g_scg[b * SS + s] = p;
    }
}

// attn phase B: redundant softmax per CTA + quarter-d wctx
__device__ __forceinline__ void attnB_phase(
    int t, float* __restrict__ attns, SmemAttn* sm, float* sc, float* red) {
    const int tid = threadIdx.x;
    const int b = blockIdx.x >> 2;
    const int q = blockIdx.x & 3;
    const int lane = tid & 31, wid = tid >> 5;

    if (tid < SS) sc[tid] = g_scg[b * SS + tid];
    __syncthreads();

    float v = (tid < 128) ? sc[tid] : -1e30f;
    float m = v;
    #pragma unroll
    for (int off = 16; off; off >>= 1) m = fmaxf(m, __shfl_xor_sync(~0u, m, off));
    if (tid < 128 && lane == 0) red[wid] = m;
    __syncthreads();
    m = fmaxf(fmaxf(red[0], red[1]), fmaxf(red[2], red[3]));
    float ex = (tid < 128) ? __expf(v - m) : 0.f;
    float ssum = ex;
    #pragma unroll
    for (int off = 16; off; off >>= 1) ssum += __shfl_xor_sync(~0u, ssum, off);
    if (tid < 128 && lane == 0) red[4 + wid] = ssum;
    __syncthreads();
    ssum = red[4] + red[5] + red[6] + red[7];
    __syncthreads();
    if (tid < 128) {
        float a = ex / ssum;
        sc[tid] = a;
        if (q == 0) attns[((size_t)b * TT + t) * SS + tid] = a;
    }
    __syncthreads();

    // wctx for d in [q*256, q*256+256): 4 s-groups x 64 d4-columns
    const int g = tid >> 6, j = tid & 63;
    const int d4 = q * 256 + j * 4;
    float4 a4 = make_float4(0.f, 0.f, 0.f, 0.f);
    for (int s = g * 32; s < g * 32 + 32; s++) {
        float as = sc[s];
        uint2 vv = *(const uint2*)(g_ctx16 + (size_t)(s * BB + b) * DD + d4);
        const __half2* hh = (const __half2*)&vv;
        float2 f0 = __half22float2(hh[0]);
        float2 f1 = __half22float2(hh[1]);
        a4.x += as * f0.x; a4.y += as * f0.y;
        a4.z += as * f1.x; a4.w += as * f1.y;
    }
    sm->wbuf[g][j] = a4;
    __syncthreads();
    if (g == 0) {
        float4 r0 = sm->wbuf[0][j], r1 = sm->wbuf[1][j], r2 = sm->wbuf[2][j], r3 = sm->wbuf[3][j];
        float4 o = make_float4(r0.x + r1.x + r2.x + r3.x, r0.y + r1.y + r2.y + r3.y,
                               r0.z + r1.z + r2.z + r3.z, r0.w + r1.w + r2.w + r3.w);
        *(float4*)&g_wctx[b][d4] = o;
    }
    __syncthreads();
}

__device__ __forceinline__ void outred_phase(int t, float* __restrict__ outs) {
    int e = blockIdx.x * NTHR + threadIdx.x;    // 65536
    int b = e & 63, d = e >> 6;
    float s = 0.f;
    #pragma unroll
    for (int ks = 0; ks < 32; ks++)
        s += g_part[((size_t)ks * 1024 + d) * 64 + b];
    float v = tanhf(s);
    g_out[b][d] = v;
    outs[((size_t)b * TT + t) * DD + d] = v;
}

// ---------------- persistent kernel: all 128 timesteps ----------------
__global__ __launch_bounds__(NTHR, 2) void main_kernel(
    float* __restrict__ outs, float* __restrict__ attns) {
    extern __shared__ char dynsm[];
    SmemU* sm = (SmemU*)dynsm;
    __shared__ const float* rp1[64];
    __shared__ const float* rp2[64];
    __shared__ float sc[SS];
    __shared__ float red[8];
    const int tid = threadIdx.x;
    const int bid = blockIdx.x;

    const int rb0 = (bid & 31) * 128, ks0 = (bid >> 5) * 256;  // lstm: 32rt x 8ks
    const int rbO = (bid & 7) * 128,  ksO = (bid >> 3) * 64;   // out:  8rt x 32ks

    for (int t = 0; t < TT; t++) {
        // lstm0 gates: x = [out | h0], K=2048
        if (tid < 64) { rp1[tid] = &g_out[tid][0]; rp2[tid] = &g_h0[tid][0]; }
        __syncthreads();
        gemm_async(rb0, ks0, 256, g_Wf0, 128, rp1, rp2, DD,
                   g_part + (size_t)(bid >> 5) * 4096 * 64, &sm->g, 0, 0);
        grid_barrier();
        cell_phase(0, t);
        grid_barrier();
        // lstm1 gates: x = [h0 | h1]
        if (tid < 64) { rp1[tid] = &g_h0[tid][0]; rp2[tid] = &g_h1[tid][0]; }
        __syncthreads();
        gemm_async(rb0, ks0, 256, g_Wf1, 128, rp1, rp2, DD,
                   g_part + (size_t)(bid >> 5) * 4096 * 64, &sm->g, 0, 0);
        grid_barrier();
        cell_phase(1, t);
        grid_barrier();
        attnA_phase(&sm->a);
        grid_barrier();
        attnB_phase(t, attns, &sm->a, sc, red);
        grid_barrier();
        // out gemm: x = [wctx | h1]
        if (tid < 64) { rp1[tid] = &g_wctx[tid][0]; rp2[tid] = &g_h1[tid][0]; }
        __syncthreads();
        gemm_async(rbO, ksO, 64, g_WfO, 128, rp1, rp2, DD,
                   g_part + (size_t)(bid >> 3) * 1024 * 64, &sm->g, 0, 0);
        grid_barrier();
        outred_phase(t, outs);
        grid_barrier();     // next step's lstm0 reads g_out
    }
}

// ---------------- final ----------------
__global__ void final_kernel(float* __restrict__ hout, float* __restrict__ cout) {
    int i = blockIdx.x * blockDim.x + threadIdx.x;
    if (i < BB * DD) {
        hout[i]           = ((float*)g_h0)[i];
        hout[BB * DD + i] = ((float*)g_h1)[i];
        cout[i]           = ((float*)g_c0)[i];
        cout[BB * DD + i] = ((float*)g_c1)[i];
    }
}

// ---------------- launch ----------------
extern "C" void kernel_launch(void* const* d_in, const int* in_sizes, int n_in,
                              void* d_out, int out_size) {
    const int*   input    = (const int*)d_in[0];
    const float* h0       = (const float*)d_in[2];
    const float* c0       = (const float*)d_in[3];
    const float* context  = (const float*)d_in[4];
    const float* init_out = (const float*)d_in[5];
    const float* word_lut = (const float*)d_in[6];
    const float* Wih0 = (const float*)d_in[7];
    const float* Whh0 = (const float*)d_in[8];
    const float* bih0 = (const float*)d_in[9];
    const float* bhh0 = (const float*)d_in[10];
    const float* Wih1 = (const float*)d_in[11];
    const float* Whh1 = (const float*)d_in[12];
    const float* bih1 = (const float*)d_in[13];
    const float* bhh1 = (const float*)d_in[14];
    const float* Win  = (const float*)d_in[15];
    const float* Wout = (const float*)d_in[16];

    float* out   = (float*)d_out;
    float* outs  = out;                           // [B,T,D]
    float* hout  = out + (size_t)BB * TT * DD;    // [2,B,D]
    float* cout  = hout + 2 * BB * DD;            // [2,B,D]
    float* attns = cout + 2 * BB * DD;            // [B,T,S]

    cudaFuncSetAttribute(main_kernel, cudaFuncAttributeMaxDynamicSharedMemorySize,
                         (int)sizeof(SmemU));
    cudaFuncSetAttribute(pre_emb_kernel, cudaFuncAttributeMaxDynamicSharedMemorySize,
                         (int)sizeof(SmemGemm));
    cudaFuncSetAttribute(cq16_kernel, cudaFuncAttributeMaxDynamicSharedMemorySize,
                         (int)sizeof(SmemGemm));

    init_kernel<<<256, 256>>>(h0, c0, init_out, bih0, bhh0, bih1, bhh1);
    ctx16_kernel<<<32768, 256>>>(context);
    // packs: (W1, ld1, off1, W2, ld2, K1w, K16tot, mbTot, which, trans)
    pack_kernel<<<1024, 256>>>(Wih0, 1536, 0,   Wih0, 1536, 512,  32,  256, 0, 0);
    pack_kernel<<<4096, 256>>>(Wih0, 1536, 512, Whh0, 1024, 1024, 128, 256, 1, 0);
    pack_kernel<<<4096, 256>>>(Wih1, 1024, 0,   Whh1, 1024, 1024, 128, 256, 2, 0);
    pack_kernel<<<1024, 256>>>(Wout, 2048, 0,   Wout, 2048, 2048, 128, 64,  3, 0);
    pack_kernel<<<512, 256>>>(Win,  1024, 0,   Win,  1024, 1024, 64,  64,  4, 1);
    cq16_kernel<<<dim3(8, 128), NTHR, sizeof(SmemGemm)>>>(context);
    pre_emb_kernel<<<dim3(32, 128), NTHR, sizeof(SmemGemm)>>>(input, word_lut);
    main_kernel<<<NCTA, NTHR, sizeof(SmemU)>>>(outs, attns);
    final_kernel<<<256, 256>>>(hout, cout);
}